// round 2
// baseline (speedup 1.0000x reference)
#include <cuda_runtime.h>

#define NX       1024
#define NTOP     5
#define THREADS  128
#define EPT      8      // elements per thread (NX / THREADS)
#define NITER    26     // bisection iterations: 14 * 2^-26 ~ 2e-7

// Insert v into descending top-6 list.
__device__ __forceinline__ void insert6(float* top, float v) {
    if (v > top[5]) {
        top[5] = v;
        #pragma unroll
        for (int j = 4; j >= 0; --j) {
            if (top[j + 1] > top[j]) {
                float t = top[j]; top[j] = top[j + 1]; top[j + 1] = t;
            }
        }
    }
}

__global__ __launch_bounds__(THREADS)
void lml_kernel(const float* __restrict__ x, float* __restrict__ y, int rows) {
    const int row = blockIdx.x;
    if (row >= rows) return;
    const int tid  = threadIdx.x;
    const int warp = tid >> 5;
    const int lane = tid & 31;

    const float* xr = x + (size_t)row * NX;

    // ---- Load row into registers (one HBM read) ----
    float4 a = reinterpret_cast<const float4*>(xr)[tid * 2 + 0];
    float4 b = reinterpret_cast<const float4*>(xr)[tid * 2 + 1];
    float xv[EPT] = {a.x, a.y, a.z, a.w, b.x, b.y, b.z, b.w};

    // ---- Per-thread top-6 ----
    float top[6];
    #pragma unroll
    for (int j = 0; j < 6; ++j) top[j] = -3.0e38f;
    #pragma unroll
    for (int j = 0; j < EPT; ++j) insert6(top, xv[j]);

    // ---- Warp-level merge of top-6 lists (butterfly) ----
    #pragma unroll
    for (int off = 16; off; off >>= 1) {
        float o[6];
        #pragma unroll
        for (int j = 0; j < 6; ++j) o[j] = __shfl_xor_sync(0xffffffffu, top[j], off);
        #pragma unroll
        for (int j = 0; j < 6; ++j) insert6(top, o[j]);
    }

    __shared__ float s_top[4][6];
    __shared__ float s_red[2][4];
    __shared__ float s_bracket[2];

    if (lane == 0) {
        #pragma unroll
        for (int j = 0; j < 6; ++j) s_top[warp][j] = top[j];
    }
    __syncthreads();

    if (tid == 0) {
        float m[6];
        #pragma unroll
        for (int j = 0; j < 6; ++j) m[j] = s_top[0][j];
        for (int w = 1; w < 4; ++w)
            #pragma unroll
            for (int j = 0; j < 6; ++j) insert6(m, s_top[w][j]);
        s_bracket[0] = -m[NTOP - 1] - 7.0f;   // f(lo) < 0  (reference nu_lower)
        s_bracket[1] = -m[NTOP]     + 7.0f;   // f(hi) > 0  (reference nu_upper)
    }
    __syncthreads();

    // Every thread holds the bracket redundantly; updates are deterministic
    // and identical across threads (same partials read in same order).
    float lo = s_bracket[0];
    float hi = s_bracket[1];

    // ---- Pure bisection on f(nu) = sum_j sigmoid(x_j + nu) - NTOP ----
    for (int it = 0; it < NITER; ++it) {
        const float nu = 0.5f * (lo + hi);
        float f = 0.f;
        #pragma unroll
        for (int j = 0; j < EPT; ++j) {
            float e = __expf(xv[j] + nu);
            f += __fdividef(e, 1.0f + e);
        }
        #pragma unroll
        for (int off = 16; off; off >>= 1)
            f += __shfl_xor_sync(0xffffffffu, f, off);
        if (lane == 0) s_red[it & 1][warp] = f;
        __syncthreads();
        float fs = (s_red[it & 1][0] + s_red[it & 1][1])
                 + (s_red[it & 1][2] + s_red[it & 1][3]) - (float)NTOP;
        if (fs < 0.f) lo = nu; else hi = nu;
        // Double-buffered s_red: iteration it+1 writes the other buffer, so a
        // single barrier per iteration is race-free.
    }

    const float nu = 0.5f * (lo + hi);

    // ---- Final output: y = sigmoid(x + nu) ----
    #pragma unroll
    for (int j = 0; j < EPT; ++j) {
        float e = __expf(xv[j] + nu);
        xv[j] = __fdividef(e, 1.0f + e);
    }
    float4* yr = reinterpret_cast<float4*>(y + (size_t)row * NX);
    yr[tid * 2 + 0] = make_float4(xv[0], xv[1], xv[2], xv[3]);
    yr[tid * 2 + 1] = make_float4(xv[4], xv[5], xv[6], xv[7]);
}

extern "C" void kernel_launch(void* const* d_in, const int* in_sizes, int n_in,
                              void* d_out, int out_size) {
    const float* x = (const float*)d_in[0];
    float* y = (float*)d_out;
    int rows = in_sizes[0] / NX;
    lml_kernel<<<rows, THREADS>>>(x, y, rows);
}

// round 3
// speedup vs baseline: 1.6612x; 1.6612x over previous
#include <cuda_runtime.h>

#define NX       1024
#define NTOP     5
#define THREADS  128
#define EPT      8      // elements per thread (NX / THREADS)
#define NBISECT  5      // bracket <= ~15.5 -> <= 0.49, midpoint err <= 0.25
#define NNEWTON  3      // 0.25 -> 0.066 -> 0.0046 -> 2.1e-5 (guaranteed, |f''|<=f')
#define LOG2E    1.4426950408889634f

__device__ __forceinline__ float ex2f(float x) {
    float r; asm("ex2.approx.f32 %0, %1;" : "=f"(r) : "f"(x)); return r;
}
__device__ __forceinline__ float rcpf(float x) {
    float r; asm("rcp.approx.f32 %0, %1;" : "=f"(r) : "f"(x)); return r;
}

// Insert v into descending top-6 list.
__device__ __forceinline__ void insert6(float* top, float v) {
    if (v > top[5]) {
        top[5] = v;
        #pragma unroll
        for (int j = 4; j >= 0; --j) {
            if (top[j + 1] > top[j]) {
                float t = top[j]; top[j] = top[j + 1]; top[j + 1] = t;
            }
        }
    }
}

__global__ __launch_bounds__(THREADS)
void lml_kernel(const float* __restrict__ x, float* __restrict__ y, int rows) {
    const int row = blockIdx.x;
    if (row >= rows) return;
    const int tid  = threadIdx.x;
    const int warp = tid >> 5;
    const int lane = tid & 31;

    const float* xr = x + (size_t)row * NX;

    // ---- Load row into registers (one HBM read) ----
    float4 a = reinterpret_cast<const float4*>(xr)[tid * 2 + 0];
    float4 b = reinterpret_cast<const float4*>(xr)[tid * 2 + 1];
    float xv[EPT] = {a.x, a.y, a.z, a.w, b.x, b.y, b.z, b.w};

    // ---- Per-thread top-6 ----
    float top[6];
    #pragma unroll
    for (int j = 0; j < 6; ++j) top[j] = -3.0e38f;
    #pragma unroll
    for (int j = 0; j < EPT; ++j) insert6(top, xv[j]);

    // ---- Warp-level merge of top-6 lists (butterfly) ----
    #pragma unroll
    for (int off = 16; off; off >>= 1) {
        float o[6];
        #pragma unroll
        for (int j = 0; j < 6; ++j) o[j] = __shfl_xor_sync(0xffffffffu, top[j], off);
        #pragma unroll
        for (int j = 0; j < 6; ++j) insert6(top, o[j]);
    }

    __shared__ float s_top[4][6];
    __shared__ float s_red[2][4][2];   // [buf][warp][f,g]
    __shared__ float s_bracket[2];

    if (lane == 0) {
        #pragma unroll
        for (int j = 0; j < 6; ++j) s_top[warp][j] = top[j];
    }
    __syncthreads();

    if (tid == 0) {
        float m[6];
        #pragma unroll
        for (int j = 0; j < 6; ++j) m[j] = s_top[0][j];
        for (int w = 1; w < 4; ++w)
            #pragma unroll
            for (int j = 0; j < 6; ++j) insert6(m, s_top[w][j]);
        s_bracket[0] = -m[NTOP - 1] - 7.0f;   // f(lo) < 0  (reference nu_lower)
        s_bracket[1] = -m[NTOP]     + 7.0f;   // f(hi) > 0  (reference nu_upper)
    }

    // Precompute xn = -x * log2(e); sigmoid(x+nu) = rcp(1 + ex2(xn - nu*log2e)).
    #pragma unroll
    for (int j = 0; j < EPT; ++j) xv[j] *= -LOG2E;

    __syncthreads();
    // Every thread holds the bracket redundantly; all updates are computed
    // identically from the same shared partials.
    float lo = s_bracket[0];
    float hi = s_bracket[1];

    int buf = 0;
    float nu;

    // ---- Phase 1: 5 bisections on f(nu) = sum sigmoid(x+nu) - NTOP ----
    #pragma unroll 1
    for (int it = 0; it < NBISECT; ++it) {
        nu = 0.5f * (lo + hi);
        const float nun = -nu * LOG2E;
        float f = 0.f;
        #pragma unroll
        for (int j = 0; j < EPT; ++j)
            f += rcpf(1.0f + ex2f(xv[j] + nun));
        #pragma unroll
        for (int off = 16; off; off >>= 1)
            f += __shfl_xor_sync(0xffffffffu, f, off);
        if (lane == 0) s_red[buf][warp][0] = f;
        __syncthreads();
        float fs = (s_red[buf][0][0] + s_red[buf][1][0])
                 + (s_red[buf][2][0] + s_red[buf][3][0]);
        if (fs < (float)NTOP) lo = nu; else hi = nu;
        buf ^= 1;   // next iteration writes the other buffer: 1 barrier/iter
    }

    nu = 0.5f * (lo + hi);

    // ---- Phase 2: 3 unguarded Newton steps (contraction proven: |f''|<=f') ----
    #pragma unroll 1
    for (int it = 0; it < NNEWTON; ++it) {
        const float nun = -nu * LOG2E;
        float f = 0.f, g = 0.f;
        #pragma unroll
        for (int j = 0; j < EPT; ++j) {
            float r = rcpf(1.0f + ex2f(xv[j] + nun));
            f += r;
            g += r * r;
        }
        #pragma unroll
        for (int off = 16; off; off >>= 1) {
            f += __shfl_xor_sync(0xffffffffu, f, off);
            g += __shfl_xor_sync(0xffffffffu, g, off);
        }
        if (lane == 0) { s_red[buf][warp][0] = f; s_red[buf][warp][1] = g; }
        __syncthreads();
        float fs = (s_red[buf][0][0] + s_red[buf][1][0])
                 + (s_red[buf][2][0] + s_red[buf][3][0]);
        float gs = (s_red[buf][0][1] + s_red[buf][1][1])
                 + (s_red[buf][2][1] + s_red[buf][3][1]);
        float fp = fs - gs;                      // f' = sum r(1-r) > 0
        nu -= (fs - (float)NTOP) / fp;           // Newton (deterministic everywhere)
        buf ^= 1;
    }

    // ---- Final output: y = sigmoid(x + nu) ----
    const float nun = -nu * LOG2E;
    #pragma unroll
    for (int j = 0; j < EPT; ++j)
        xv[j] = rcpf(1.0f + ex2f(xv[j] + nun));

    float4* yr = reinterpret_cast<float4*>(y + (size_t)row * NX);
    yr[tid * 2 + 0] = make_float4(xv[0], xv[1], xv[2], xv[3]);
    yr[tid * 2 + 1] = make_float4(xv[4], xv[5], xv[6], xv[7]);
}

extern "C" void kernel_launch(void* const* d_in, const int* in_sizes, int n_in,
                              void* d_out, int out_size) {
    const float* x = (const float*)d_in[0];
    float* y = (float*)d_out;
    int rows = in_sizes[0] / NX;
    lml_kernel<<<rows, THREADS>>>(x, y, rows);
}

// round 4
// speedup vs baseline: 3.4995x; 2.1066x over previous
#include <cuda_runtime.h>

#define NX       1024
#define NTOP     5
#define THREADS  128
#define RPB      4      // rows per block (one warp per row)
#define EPT      32     // elements per lane (NX / 32)
#define NBISECT  7      // sloppy tanh bisections
#define NNEWTON  2      // exact Newton steps (|f''| <= f' => quadratic, unguarded-safe)
#define LOG2E    1.4426950408889634f

__device__ __forceinline__ float ex2f(float x) {
    float r; asm("ex2.approx.f32 %0, %1;" : "=f"(r) : "f"(x)); return r;
}
__device__ __forceinline__ float rcpf(float x) {
    float r; asm("rcp.approx.f32 %0, %1;" : "=f"(r) : "f"(x)); return r;
}
__device__ __forceinline__ float tanhf_a(float x) {
    float r; asm("tanh.approx.f32 %0, %1;" : "=f"(r) : "f"(x)); return r;
}

__global__ __launch_bounds__(THREADS, 8)
void lml_kernel(const float* __restrict__ x, float* __restrict__ y, int rows) {
    const int warp = threadIdx.x >> 5;
    const int lane = threadIdx.x & 31;
    const int row  = blockIdx.x * RPB + warp;
    if (row >= rows) return;

    const float4* xr = reinterpret_cast<const float4*>(x + (size_t)row * NX);

    // ---- Load row: 8 coalesced float4 per lane (one HBM read) ----
    float xv[EPT];
    #pragma unroll
    for (int k = 0; k < 8; ++k) {
        float4 v = xr[lane + 32 * k];
        xv[4 * k + 0] = v.x; xv[4 * k + 1] = v.y;
        xv[4 * k + 2] = v.z; xv[4 * k + 3] = v.w;
    }

    // ---- Bracket from row min/max (guaranteed):
    //   f(-max-7) <= 1024*sigmoid(-7) = 0.93 < 5
    //   f(-min+7) >= 1024*sigmoid(+7) ~ 1023  > 5
    float mx = xv[0], mn = xv[0];
    #pragma unroll
    for (int j = 1; j < EPT; ++j) { mx = fmaxf(mx, xv[j]); mn = fminf(mn, xv[j]); }
    #pragma unroll
    for (int off = 16; off; off >>= 1) {
        mx = fmaxf(mx, __shfl_xor_sync(0xffffffffu, mx, off));
        mn = fminf(mn, __shfl_xor_sync(0xffffffffu, mn, off));
    }
    float lo = -mx - 7.0f;
    float hi = -mn + 7.0f;

    // ---- Phase 1: sloppy bisection, 1 MUFU per element.
    // sigmoid(z) = 0.5*(1 + tanh(z/2));  sum sigmoid < 5  <=>  sum tanh < -1014.
    float nu;
    #pragma unroll 1
    for (int it = 0; it < NBISECT; ++it) {
        nu = 0.5f * (lo + hi);
        const float hnu = 0.5f * nu;
        float f = 0.f;
        #pragma unroll
        for (int j = 0; j < EPT; ++j)
            f += tanhf_a(fmaf(0.5f, xv[j], hnu));
        #pragma unroll
        for (int off = 16; off; off >>= 1)
            f += __shfl_xor_sync(0xffffffffu, f, off);
        if (f < -(float)(2 * (NX - 2 * NTOP) / 2)) lo = nu; else hi = nu;  // -1014
    }
    nu = 0.5f * (lo + hi);

    // ---- Phase 2: exact unguarded Newton (ex2 + rcp), quadratic contraction.
    #pragma unroll 1
    for (int it = 0; it < NNEWTON; ++it) {
        const float c = -nu * LOG2E;
        float f = 0.f, g = 0.f;
        #pragma unroll
        for (int j = 0; j < EPT; ++j) {
            // sigmoid(x+nu) = 1 / (1 + 2^(-(x+nu)*log2e))
            float r = rcpf(1.0f + ex2f(fmaf(-LOG2E, xv[j], c)));
            f += r;
            g = fmaf(r, r, g);
        }
        #pragma unroll
        for (int off = 16; off; off >>= 1) {
            f += __shfl_xor_sync(0xffffffffu, f, off);
            g += __shfl_xor_sync(0xffffffffu, g, off);
        }
        float fp = f - g;                          // f' = sum r(1-r) > 0
        nu -= __fdividef(f - (float)NTOP, fp);     // identical across lanes
    }

    // ---- Final output: y = sigmoid(x + nu) ----
    const float c = -nu * LOG2E;
    #pragma unroll
    for (int j = 0; j < EPT; ++j)
        xv[j] = rcpf(1.0f + ex2f(fmaf(-LOG2E, xv[j], c)));

    float4* yr = reinterpret_cast<float4*>(y + (size_t)row * NX);
    #pragma unroll
    for (int k = 0; k < 8; ++k)
        yr[lane + 32 * k] = make_float4(xv[4 * k + 0], xv[4 * k + 1],
                                        xv[4 * k + 2], xv[4 * k + 3]);
}

extern "C" void kernel_launch(void* const* d_in, const int* in_sizes, int n_in,
                              void* d_out, int out_size) {
    const float* x = (const float*)d_in[0];
    float* y = (float*)d_out;
    int rows = in_sizes[0] / NX;
    lml_kernel<<<(rows + RPB - 1) / RPB, THREADS>>>(x, y, rows);
}

// round 5
// speedup vs baseline: 3.5263x; 1.0077x over previous
#include <cuda_runtime.h>
#include <cstdint>

#define NX       1024
#define NTOP     5
#define THREADS  128
#define RPB      4      // rows per block (one warp per row)
#define EPT      32     // elements per lane
#define NBISECT  7      // bf16x2 sloppy bisections (0.5 MUFU/elem each)
#define NHALLEY  2      // exact cubic-convergent steps: e' <= 0.42 e^3
#define LOG2E    1.4426950408889634f

__device__ __forceinline__ float ex2f(float x) {
    float r; asm("ex2.approx.f32 %0, %1;" : "=f"(r) : "f"(x)); return r;
}
__device__ __forceinline__ float rcpf(float x) {
    float r; asm("rcp.approx.f32 %0, %1;" : "=f"(r) : "f"(x)); return r;
}
__device__ __forceinline__ uint32_t pack_bf16x2(float a, float b) {
    uint32_t r; asm("cvt.rn.bf16x2.f32 %0, %1, %2;" : "=r"(r) : "f"(a), "f"(b)); return r;
}
__device__ __forceinline__ uint32_t add_bf16x2(uint32_t a, uint32_t b) {
    uint32_t r; asm("add.rn.bf16x2 %0, %1, %2;" : "=r"(r) : "r"(a), "r"(b)); return r;
}
__device__ __forceinline__ uint32_t tanh_bf16x2(uint32_t a) {
    uint32_t r; asm("tanh.approx.bf16x2 %0, %1;" : "=r"(r) : "r"(a)); return r;
}

__global__ __launch_bounds__(THREADS, 6)
void lml_kernel(const float* __restrict__ x, float* __restrict__ y, int rows) {
    const int warp = threadIdx.x >> 5;
    const int lane = threadIdx.x & 31;
    const int row  = blockIdx.x * RPB + warp;
    if (row >= rows) return;

    const float4* xr = reinterpret_cast<const float4*>(x + (size_t)row * NX);

    // ---- Load row: 8 coalesced float4 per lane (one HBM read) ----
    float xv[EPT];
    #pragma unroll
    for (int k = 0; k < 8; ++k) {
        float4 v = xr[lane + 32 * k];
        xv[4 * k + 0] = v.x; xv[4 * k + 1] = v.y;
        xv[4 * k + 2] = v.z; xv[4 * k + 3] = v.w;
    }

    // ---- Bracket from row min/max (guaranteed sign change):
    //   f(-max-7) <= 1024*sigmoid(-7) = 0.93 < 5;  f(-min+7) >= 1024*sigmoid(7) > 5
    float mx = xv[0], mn = xv[0];
    #pragma unroll
    for (int j = 1; j < EPT; ++j) { mx = fmaxf(mx, xv[j]); mn = fminf(mn, xv[j]); }
    #pragma unroll
    for (int off = 16; off; off >>= 1) {
        mx = fmaxf(mx, __shfl_xor_sync(0xffffffffu, mx, off));
        mn = fminf(mn, __shfl_xor_sync(0xffffffffu, mn, off));
    }
    float lo = -mx - 7.0f;
    float hi = -mn + 7.0f;

    // ---- Pre-pack x/2 as bf16x2 pairs (sloppy-phase operand) ----
    uint32_t hx[EPT / 2];
    #pragma unroll
    for (int k = 0; k < EPT / 2; ++k)
        hx[k] = pack_bf16x2(0.5f * xv[2 * k], 0.5f * xv[2 * k + 1]);

    // ---- Phase 1: sloppy bisection, 0.5 MUFU/elem.
    // sigmoid(z) = (1 + tanh(z/2))/2;  sum sigmoid < 5  <=>  sum tanh < -1014.
    float nu;
    #pragma unroll 1
    for (int it = 0; it < NBISECT; ++it) {
        nu = 0.5f * (lo + hi);
        const float    hnu = 0.5f * nu;
        const uint32_t hn  = pack_bf16x2(hnu, hnu);
        float f = 0.f;
        #pragma unroll
        for (int k = 0; k < EPT / 2; ++k) {
            uint32_t t = tanh_bf16x2(add_bf16x2(hx[k], hn));
            f += __uint_as_float(t << 16);            // bf16 lo -> f32 (exact)
            f += __uint_as_float(t & 0xffff0000u);    // bf16 hi -> f32 (exact)
        }
        #pragma unroll
        for (int off = 16; off; off >>= 1)
            f += __shfl_xor_sync(0xffffffffu, f, off);
        if (f < -(float)(NX - 2 * NTOP)) lo = nu; else hi = nu;   // -1014
    }
    nu = 0.5f * (lo + hi);

    // ---- Phase 2: exact Halley steps (A=sum s, B=sum s^2, C=sum s^3).
    // f' = A - B,  f'' = A - 3B + 2C;  |f''|<=f', |f'''|<=f' => e' <= 0.42 e^3.
    #pragma unroll 1
    for (int it = 0; it < NHALLEY; ++it) {
        const float c = -nu * LOG2E;
        float A = 0.f, B = 0.f, C = 0.f;
        #pragma unroll
        for (int j = 0; j < EPT; ++j) {
            float r  = rcpf(1.0f + ex2f(fmaf(-LOG2E, xv[j], c)));  // exact sigmoid
            float r2 = r * r;
            A += r;
            B = fmaf(r, r, B);
            C = fmaf(r2, r, C);
        }
        #pragma unroll
        for (int off = 16; off; off >>= 1) {
            A += __shfl_xor_sync(0xffffffffu, A, off);
            B += __shfl_xor_sync(0xffffffffu, B, off);
            C += __shfl_xor_sync(0xffffffffu, C, off);
        }
        float fv  = A - (float)NTOP;
        float fp  = A - B;                       // > 0
        float fpp = fmaf(2.0f, C, A) - 3.0f * B;
        float den = fmaf(2.0f, fp * fp, -fv * fpp);   // >= 2f'^2(1-e/2) > 0
        nu -= __fdividef(2.0f * fv * fp, den);   // identical across lanes
    }

    // ---- Final output: y = sigmoid(x + nu), exact f32 path ----
    const float c = -nu * LOG2E;
    #pragma unroll
    for (int j = 0; j < EPT; ++j)
        xv[j] = rcpf(1.0f + ex2f(fmaf(-LOG2E, xv[j], c)));

    float4* yr = reinterpret_cast<float4*>(y + (size_t)row * NX);
    #pragma unroll
    for (int k = 0; k < 8; ++k)
        yr[lane + 32 * k] = make_float4(xv[4 * k + 0], xv[4 * k + 1],
                                        xv[4 * k + 2], xv[4 * k + 3]);
}

extern "C" void kernel_launch(void* const* d_in, const int* in_sizes, int n_in,
                              void* d_out, int out_size) {
    const float* x = (const float*)d_in[0];
    float* y = (float*)d_out;
    int rows = in_sizes[0] / NX;
    lml_kernel<<<(rows + RPB - 1) / RPB, THREADS>>>(x, y, rows);
}

// round 6
// speedup vs baseline: 4.4237x; 1.2545x over previous
#include <cuda_runtime.h>

#define NX       1024
#define NTOP     5
#define THREADS  128
#define RPB      4      // rows per block (one warp per row)
#define EPT      32     // elements per lane
#define NBISECT  5      // bracket width ~(mx-mn)+0.9 -> e0 <= ~0.23
#define LOG2E    1.4426950408889634f

__device__ __forceinline__ float ex2f(float x) {
    float r; asm("ex2.approx.f32 %0, %1;" : "=f"(r) : "f"(x)); return r;
}
__device__ __forceinline__ float rcpf(float x) {
    float r; asm("rcp.approx.f32 %0, %1;" : "=f"(r) : "f"(x)); return r;
}
__device__ __forceinline__ float tanhf_a(float x) {
    float r; asm("tanh.approx.f32 %0, %1;" : "=f"(r) : "f"(x)); return r;
}

__global__ __launch_bounds__(THREADS, 8)
void lml_kernel(const float* __restrict__ x, float* __restrict__ y, int rows) {
    const int warp = threadIdx.x >> 5;
    const int lane = threadIdx.x & 31;
    const int row  = blockIdx.x * RPB + warp;
    if (row >= rows) return;

    const float4* xr = reinterpret_cast<const float4*>(x + (size_t)row * NX);

    // ---- Load row: 8 coalesced float4 per lane (one HBM read) ----
    float xv[EPT];
    #pragma unroll
    for (int k = 0; k < 8; ++k) {
        float4 v = xr[lane + 32 * k];
        xv[4 * k + 0] = v.x; xv[4 * k + 1] = v.y;
        xv[4 * k + 2] = v.z; xv[4 * k + 3] = v.w;
    }

    // ---- Tight guaranteed bracket from row min/max:
    //   lo = -mx-5.8 : every arg <= -5.8, sum <= 1024*sigmoid(-5.8) = 3.1 < 5
    //   hi = -mn-4.9 : every arg >= -4.9, sum >= 1024*sigmoid(-4.9) = 7.6 > 5
    float mx = xv[0], mn = xv[0];
    #pragma unroll
    for (int j = 1; j < EPT; ++j) { mx = fmaxf(mx, xv[j]); mn = fminf(mn, xv[j]); }
    #pragma unroll
    for (int off = 16; off; off >>= 1) {
        mx = fmaxf(mx, __shfl_xor_sync(0xffffffffu, mx, off));
        mn = fminf(mn, __shfl_xor_sync(0xffffffffu, mn, off));
    }
    float lo = -mx - 5.8f;
    float hi = -mn - 4.9f;

    // ---- Phase 1: 5 sloppy bisections, 1 MUFU/elem each.
    // sigmoid(z) = (1 + tanh(z/2))/2;  sum sigmoid < 5  <=>  sum tanh < -1014.
    float nu;
    #pragma unroll 1
    for (int it = 0; it < NBISECT; ++it) {
        nu = 0.5f * (lo + hi);
        const float hnu = 0.5f * nu;
        float f = 0.f;
        #pragma unroll
        for (int j = 0; j < EPT; ++j)
            f += tanhf_a(fmaf(0.5f, xv[j], hnu));
        #pragma unroll
        for (int off = 16; off; off >>= 1)
            f += __shfl_xor_sync(0xffffffffu, f, off);
        if (f < -(float)(NX - 2 * NTOP)) lo = nu; else hi = nu;   // -1014
    }
    nu = 0.5f * (lo + hi);

    // ---- Phase 2: one exact Halley step (cubic: e' <= 0.42 e^3).
    // A = sum s, B = sum s^2, C = sum s^3;  f' = A-B,  f'' = A-3B+2C.
    {
        const float c = -nu * LOG2E;
        float A = 0.f, B = 0.f, C = 0.f;
        #pragma unroll
        for (int j = 0; j < EPT; ++j) {
            float r  = rcpf(1.0f + ex2f(fmaf(-LOG2E, xv[j], c)));  // exact sigmoid
            A += r;
            B = fmaf(r, r, B);
            C = fmaf(r * r, r, C);
        }
        #pragma unroll
        for (int off = 16; off; off >>= 1) {
            A += __shfl_xor_sync(0xffffffffu, A, off);
            B += __shfl_xor_sync(0xffffffffu, B, off);
            C += __shfl_xor_sync(0xffffffffu, C, off);
        }
        float fv  = A - (float)NTOP;
        float fp  = A - B;                            // > 0
        float fpp = fmaf(2.0f, C, A) - 3.0f * B;
        float den = fmaf(2.0f, fp * fp, -fv * fpp);   // > 0 for e < 2
        nu -= __fdividef(2.0f * fv * fp, den);        // identical across lanes
    }

    // ---- Phase 3: final exact eval doubles as output pass.
    // Compute r_j = sigmoid(x_j + nu) once; Newton residual delta corrects the
    // output to first order: y = r + r(1-r)*delta  (delta ~ 5e-3 -> err ~1e-5).
    {
        const float c = -nu * LOG2E;
        float A = 0.f, B = 0.f;
        #pragma unroll
        for (int j = 0; j < EPT; ++j) {
            float r = rcpf(1.0f + ex2f(fmaf(-LOG2E, xv[j], c)));
            xv[j] = r;                                // stash sigmoid
            A += r;
            B = fmaf(r, r, B);
        }
        #pragma unroll
        for (int off = 16; off; off >>= 1) {
            A += __shfl_xor_sync(0xffffffffu, A, off);
            B += __shfl_xor_sync(0xffffffffu, B, off);
        }
        const float delta = -__fdividef(A - (float)NTOP, A - B);   // Newton step
        #pragma unroll
        for (int j = 0; j < EPT; ++j) {
            float r = xv[j];
            float t = fmaf(-r, r, r);                 // r(1-r)
            xv[j] = fmaf(t, delta, r);                // first-order update
        }
    }

    float4* yr = reinterpret_cast<float4*>(y + (size_t)row * NX);
    #pragma unroll
    for (int k = 0; k < 8; ++k)
        yr[lane + 32 * k] = make_float4(xv[4 * k + 0], xv[4 * k + 1],
                                        xv[4 * k + 2], xv[4 * k + 3]);
}

extern "C" void kernel_launch(void* const* d_in, const int* in_sizes, int n_in,
                              void* d_out, int out_size) {
    const float* x = (const float*)d_in[0];
    float* y = (float*)d_out;
    int rows = in_sizes[0] / NX;
    lml_kernel<<<(rows + RPB - 1) / RPB, THREADS>>>(x, y, rows);
}

// round 8
// speedup vs baseline: 4.9024x; 1.1082x over previous
#include <cuda_runtime.h>

#define NX       1024
#define NTOP     5
#define THREADS  128
#define RPB      4      // rows per block (one warp per row)
#define EPT      32     // elements per lane
#define NSLOPPY  3      // clamped Newton-on-ln(f) iterations (1 MUFU/elem each)
#define LOG2E    1.4426950408889634f
#define LN2      0.6931471805599453f
#define LOG2_5   2.3219280948873623f

__device__ __forceinline__ float ex2f(float x) {
    float r; asm("ex2.approx.f32 %0, %1;" : "=f"(r) : "f"(x)); return r;
}
__device__ __forceinline__ float rcpf(float x) {
    float r; asm("rcp.approx.f32 %0, %1;" : "=f"(r) : "f"(x)); return r;
}
__device__ __forceinline__ float tanhf_a(float x) {
    float r; asm("tanh.approx.f32 %0, %1;" : "=f"(r) : "f"(x)); return r;
}
__device__ __forceinline__ float lg2f(float x) {
    float r; asm("lg2.approx.f32 %0, %1;" : "=f"(r) : "f"(x)); return r;
}

__global__ __launch_bounds__(THREADS, 8)
void lml_kernel(const float* __restrict__ x, float* __restrict__ y, int rows) {
    const int warp = threadIdx.x >> 5;
    const int lane = threadIdx.x & 31;
    const int row  = blockIdx.x * RPB + warp;
    if (row >= rows) return;

    const float4* xr = reinterpret_cast<const float4*>(x + (size_t)row * NX);

    // ---- Load row: 8 coalesced float4 per lane (one HBM read) ----
    float xv[EPT];
    #pragma unroll
    for (int k = 0; k < 8; ++k) {
        float4 v = xr[lane + 32 * k];
        xv[4 * k + 0] = v.x; xv[4 * k + 1] = v.y;
        xv[4 * k + 2] = v.z; xv[4 * k + 3] = v.w;
    }

    // ---- Guaranteed bracket from row min/max:
    //   lo = -mx-5.8 : sum <= 1024*sigmoid(-5.8) = 3.1 < 5
    //   hi = -mn-4.9 : sum >= 1024*sigmoid(-4.9) = 7.6 > 5
    float mx = xv[0], mn = xv[0];
    #pragma unroll
    for (int j = 1; j < EPT; ++j) { mx = fmaxf(mx, xv[j]); mn = fminf(mn, xv[j]); }
    #pragma unroll
    for (int off = 16; off; off >>= 1) {
        mx = fmaxf(mx, __shfl_xor_sync(0xffffffffu, mx, off));
        mn = fminf(mn, __shfl_xor_sync(0xffffffffu, mn, off));
    }
    float lo = -mx - 5.8f;
    float hi = -mn - 4.9f;
    float nu = 0.5f * (lo + hi);

    // ---- Phase 1: 3 clamped Newton-on-ln(f) steps on the sloppy tanh model.
    // sigmoid(z) = (1+tanh(z/2))/2 => f = 512 + T1/2, f' = (1024 - T2)/4.
    // Converges to the SLOPPY f's root (displaced ~0.3 by coherent tanh.approx
    // bias); the two exact stages below remove that. Steps are clamped into the
    // maintained bracket (NaN-safe: fmaxf/fminf drop NaN operands).
    #pragma unroll 1
    for (int it = 0; it < NSLOPPY; ++it) {
        const float hnu = 0.5f * nu;
        float T1 = 0.f, T2 = 0.f;
        #pragma unroll
        for (int j = 0; j < EPT; ++j) {
            float t = tanhf_a(fmaf(0.5f, xv[j], hnu));
            T1 += t;
            T2 = fmaf(t, t, T2);
        }
        #pragma unroll
        for (int off = 16; off; off >>= 1) {
            T1 += __shfl_xor_sync(0xffffffffu, T1, off);
            T2 += __shfl_xor_sync(0xffffffffu, T2, off);
        }
        float f  = fmaf(0.5f,  T1, 512.0f);   // sum sigmoid (sloppy)
        float fp = fmaf(-0.25f, T2, 256.0f);  // sum sigmoid' (sloppy)
        if (f < (float)NTOP) lo = nu; else hi = nu;
        float nun = nu - (lg2f(f) - LOG2_5) * LN2 * f * rcpf(fp);
        float w   = hi - lo;
        nun = fmaxf(nun, fmaf(0.02f, w, lo));   // clamp into bracket interior
        nun = fminf(nun, fmaf(-0.02f, w, hi));  // (NaN in nun -> picks bounds)
        nu = nun;
    }

    // ---- Phase 2: exact Halley step (cubic: e' <= 0.42 e^3).
    // A = sum s, B = sum s^2, C = sum s^3;  f' = A-B, f'' = A-3B+2C.
    {
        const float c = -nu * LOG2E;
        float A = 0.f, B = 0.f, C = 0.f;
        #pragma unroll
        for (int j = 0; j < EPT; ++j) {
            float r = rcpf(1.0f + ex2f(fmaf(-LOG2E, xv[j], c)));  // exact sigmoid
            A += r;
            B = fmaf(r, r, B);
            C = fmaf(r * r, r, C);
        }
        #pragma unroll
        for (int off = 16; off; off >>= 1) {
            A += __shfl_xor_sync(0xffffffffu, A, off);
            B += __shfl_xor_sync(0xffffffffu, B, off);
            C += __shfl_xor_sync(0xffffffffu, C, off);
        }
        float fv  = A - (float)NTOP;
        float fp  = A - B;                             // > 0
        float fpp = fmaf(2.0f, C, A) - 3.0f * B;
        float den = fmaf(2.0f, fp * fp, -fv * fpp);    // > 0 near root
        nu -= __fdividef(2.0f * fv * fp, den);         // lane-uniform
    }

    // ---- Phase 3: exact output pass + fused Newton correction.
    // r_j computed once; delta = -(A-5)/(A-B);  y = r + r(1-r)*delta*(1+0.5(1-2r)delta).
    {
        const float c = -nu * LOG2E;
        float A = 0.f, B = 0.f;
        #pragma unroll
        for (int j = 0; j < EPT; ++j) {
            float r = rcpf(1.0f + ex2f(fmaf(-LOG2E, xv[j], c)));
            xv[j] = r;
            A += r;
            B = fmaf(r, r, B);
        }
        #pragma unroll
        for (int off = 16; off; off >>= 1) {
            A += __shfl_xor_sync(0xffffffffu, A, off);
            B += __shfl_xor_sync(0xffffffffu, B, off);
        }
        const float delta = -__fdividef(A - (float)NTOP, A - B);
        #pragma unroll
        for (int j = 0; j < EPT; ++j) {
            float r = xv[j];
            float t = fmaf(-r, r, r);                         // r(1-r)
            float u = delta * fmaf(0.5f - r, delta, 1.0f);    // 2nd-order Taylor
            xv[j] = fmaf(t, u, r);
        }
    }

    float4* yr = reinterpret_cast<float4*>(y + (size_t)row * NX);
    #pragma unroll
    for (int k = 0; k < 8; ++k)
        yr[lane + 32 * k] = make_float4(xv[4 * k + 0], xv[4 * k + 1],
                                        xv[4 * k + 2], xv[4 * k + 3]);
}

extern "C" void kernel_launch(void* const* d_in, const int* in_sizes, int n_in,
                              void* d_out, int out_size) {
    const float* x = (const float*)d_in[0];
    float* y = (float*)d_out;
    int rows = in_sizes[0] / NX;
    lml_kernel<<<(rows + RPB - 1) / RPB, THREADS>>>(x, y, rows);
}